// round 16
// baseline (speedup 1.0000x reference)
#include <cuda_runtime.h>
#include <stdint.h>

#define N_NODES   100000
#define N_EDGES   25000
#define NNZ_MAX   2000000
#define HO        64
#define IN_CH     64

#define TILE      4096
#define TE        ((N_EDGES + TILE - 1) / TILE)   // 7
#define TV        ((N_NODES + TILE - 1) / TILE)   // 25
#define NTILES    (TE + TV)                        // 32

// ---------------- scratch (device globals; no allocation) ----------------
__device__ __align__(16) float g_Xe[N_EDGES * HO];
__device__ int   g_ecnt[N_EDGES];
__device__ int   g_vcnt[N_NODES];
__device__ float g_att[N_NODES];
__device__ int   g_erow[N_EDGES + 1];
__device__ int   g_vrow[N_NODES + 1];
__device__ int   g_evid[NNZ_MAX];
__device__ int   g_veid[NNZ_MAX];
__device__ __align__(16) int g_ranke[NNZ_MAX];
__device__ __align__(16) int g_rankv[NNZ_MAX];
__device__ int   g_epart[TE];
__device__ int   g_vpart[TV];
__device__ int   g_scan_arrive;

// ---------------- side stream + fork/join events (host-side, created once) --
struct HxSideStream {
    cudaStream_t s2;
    cudaEvent_t  ev_fork, ev_join;
    HxSideStream() {
        cudaStreamCreateWithFlags(&s2, cudaStreamNonBlocking);
        cudaEventCreateWithFlags(&ev_fork, cudaEventDisableTiming);
        cudaEventCreateWithFlags(&ev_join, cudaEventDisableTiming);
    }
};
static HxSideStream g_hx;

// ---------------- kernel A: zero counters + barrier flag ----------------
__global__ void zero_kernel()
{
    int idx = blockIdx.x * blockDim.x + threadIdx.x;
    if (idx == 0) g_scan_arrive = 0;
    if (idx < N_EDGES) g_ecnt[idx] = 0;
    if (idx < N_NODES) { g_vcnt[idx] = 0; g_att[idx] = 0.f; }
}

// ---------------- kernel B1: GEMM  Xp = X @ W -> out (side stream) ----------
__global__ void gemm_kernel(const float* __restrict__ X,
                            const float* __restrict__ W,
                            float* __restrict__ out, int n)
{
    __shared__ float sW[64 * 64];
    __shared__ float sX[64 * 65];

    const int t  = threadIdx.x;
    const int r0 = blockIdx.x * 64;

    #pragma unroll
    for (int idx = t; idx < 64 * 64; idx += 256) sW[idx] = W[idx];
    #pragma unroll
    for (int idx = t; idx < 64 * 64; idx += 256) {
        int r = idx >> 6, k = idx & 63;
        int gr = r0 + r;
        sX[r * 65 + k] = (gr < n) ? X[gr * 64 + k] : 0.f;
    }
    __syncthreads();

    const int row = t >> 2;
    const int q   = t & 3;

    float4 a0 = {0,0,0,0}, a1 = {0,0,0,0}, a2 = {0,0,0,0}, a3 = {0,0,0,0};
    #pragma unroll 16
    for (int k = 0; k < 64; k++) {
        float x = sX[row * 65 + k];
        const float4* w4 = (const float4*)&sW[k * 64 + q * 16];
        float4 wa = w4[0], wb = w4[1], wc = w4[2], wd = w4[3];
        a0.x += x * wa.x; a0.y += x * wa.y; a0.z += x * wa.z; a0.w += x * wa.w;
        a1.x += x * wb.x; a1.y += x * wb.y; a1.z += x * wb.z; a1.w += x * wb.w;
        a2.x += x * wc.x; a2.y += x * wc.y; a2.z += x * wc.z; a2.w += x * wc.w;
        a3.x += x * wd.x; a3.y += x * wd.y; a3.z += x * wd.z; a3.w += x * wd.w;
    }
    int gr = r0 + row;
    if (gr < n) {
        float4* o = (float4*)&out[gr * 64 + q * 16];
        o[0] = a0; o[1] = a1; o[2] = a2; o[3] = a3;
    }
}

// ---------------- kernel B2: histogram + rank capture (main stream) ---------
__global__ void hist_kernel(const float* __restrict__ homo,
                            const int* __restrict__ vertex,
                            const int* __restrict__ edges, int nnz)
{
    int i = (blockIdx.x * blockDim.x + threadIdx.x) * 4;
    if (i + 3 < nnz) {
        int4 v = *(const int4*)&vertex[i];
        int4 e = *(const int4*)&edges[i];
        int4 re, rv;
        re.x = atomicAdd(&g_ecnt[e.x], 1);
        re.y = atomicAdd(&g_ecnt[e.y], 1);
        re.z = atomicAdd(&g_ecnt[e.z], 1);
        re.w = atomicAdd(&g_ecnt[e.w], 1);
        rv.x = atomicAdd(&g_vcnt[v.x], 1);
        rv.y = atomicAdd(&g_vcnt[v.y], 1);
        rv.z = atomicAdd(&g_vcnt[v.z], 1);
        rv.w = atomicAdd(&g_vcnt[v.w], 1);
        *(int4*)&g_ranke[i] = re;
        *(int4*)&g_rankv[i] = rv;
        atomicAdd(&g_att[v.x], homo[e.x]); atomicAdd(&g_att[v.y], homo[e.y]);
        atomicAdd(&g_att[v.z], homo[e.z]); atomicAdd(&g_att[v.w], homo[e.w]);
    } else {
        for (int k = i; k < nnz; k++) {
            int v = vertex[k], e = edges[k];
            g_ranke[k] = atomicAdd(&g_ecnt[e], 1);
            g_rankv[k] = atomicAdd(&g_vcnt[v], 1);
            atomicAdd(&g_att[v], homo[e]);
        }
    }
}

// ---------------- kernel C: fused scan (32 blocks, soft global barrier) -----
__global__ void scan_kernel()
{
    const bool is_e = blockIdx.x < TE;
    const int  tile = is_e ? blockIdx.x : blockIdx.x - TE;
    const int  n    = is_e ? N_EDGES : N_NODES;
    const int  nt   = is_e ? TE : TV;
    const int* __restrict__ cnt  = is_e ? g_ecnt : g_vcnt;
    int* __restrict__ part       = is_e ? g_epart : g_vpart;
    int* __restrict__ row        = is_e ? g_erow : g_vrow;

    __shared__ int s_wsum[32];
    __shared__ int s_tile_off;
    const int lane = threadIdx.x & 31;
    const int wid  = threadIdx.x >> 5;

    int base = tile * TILE + threadIdx.x * 4;
    int c[4];
    int s = 0;
    #pragma unroll
    for (int k = 0; k < 4; k++) {
        int i = base + k;
        c[k] = (i < n) ? cnt[i] : 0;
        s += c[k];
    }
    int v = s;
    #pragma unroll
    for (int o = 1; o < 32; o <<= 1) {
        int t = __shfl_up_sync(0xffffffffu, v, o);
        if (lane >= o) v += t;
    }
    if (lane == 31) s_wsum[wid] = v;
    __syncthreads();

    if (wid == 0) {
        int w = s_wsum[lane];
        int tot = w;
        #pragma unroll
        for (int o = 16; o; o >>= 1) tot += __shfl_xor_sync(0xffffffffu, tot, o);
        if (lane == 0) {
            part[tile] = tot;
            __threadfence();
            atomicAdd(&g_scan_arrive, 1);
        }
    }
    if (threadIdx.x == 0) {
        while (atomicAdd(&g_scan_arrive, 0) < NTILES) { }
    }
    __syncthreads();
    __threadfence();

    if (wid == 0) {
        const int* p_arr = is_e ? g_epart : g_vpart;
        int p = (lane < nt) ? p_arr[lane] : 0;
        int incl = p;
        #pragma unroll
        for (int o = 1; o < 32; o <<= 1) {
            int t = __shfl_up_sync(0xffffffffu, incl, o);
            if (lane >= o) incl += t;
        }
        if (lane == tile) s_tile_off = incl - p;
        if (tile == 0 && lane == nt - 1) row[n] = incl;

        int w = s_wsum[lane];
        int u = w;
        #pragma unroll
        for (int o = 1; o < 32; o <<= 1) {
            int t = __shfl_up_sync(0xffffffffu, u, o);
            if (lane >= o) u += t;
        }
        s_wsum[lane] = u - w;
    }
    __syncthreads();

    int excl = s_tile_off + s_wsum[wid] + (v - s);
    #pragma unroll
    for (int k = 0; k < 4; k++) {
        int i = base + k;
        if (i < n) row[i] = excl;
        excl += c[k];
    }
}

// ---------------- kernel D: edge-side scatter (atomic-free) -----------------
__global__ void permE_kernel(const int* __restrict__ vertex,
                             const int* __restrict__ edges, int nnz)
{
    int i = blockIdx.x * blockDim.x + threadIdx.x;
    if (i >= nnz) return;
    int v = vertex[i];
    int e = edges[i];
    g_evid[g_erow[e] + g_ranke[i]] = v;
}

// ---------------- kernel E: fused edge_agg + vertex-side scatter ------------
__global__ void edgeagg_permV_kernel(const float* __restrict__ Xp,
                                     const int* __restrict__ vertex,
                                     const int* __restrict__ edges,
                                     int nnz, int agg_blocks)
{
    if (blockIdx.x < agg_blocks) {
        int e = (blockIdx.x * blockDim.x + threadIdx.x) >> 5;
        if (e >= N_EDGES) return;
        const int lane = threadIdx.x & 31;
        const int h = lane >> 4;
        const int c = lane & 15;

        int beg = g_erow[e], end = g_erow[e + 1];
        float4 acc = {0.f, 0.f, 0.f, 0.f};

        #pragma unroll 2
        for (int j = beg + h; j < end; j += 2) {
            int v = g_evid[j];
            float4 x = *(const float4*)&Xp[v * 64 + c * 4];
            acc.x += x.x; acc.y += x.y; acc.z += x.z; acc.w += x.w;
        }
        acc.x += __shfl_xor_sync(0xffffffffu, acc.x, 16);
        acc.y += __shfl_xor_sync(0xffffffffu, acc.y, 16);
        acc.z += __shfl_xor_sync(0xffffffffu, acc.z, 16);
        acc.w += __shfl_xor_sync(0xffffffffu, acc.w, 16);

        int deg = end - beg;
        float inv = (deg > 0) ? (1.f / (float)deg) : 0.f;
        if (h == 0) {
            float4 r = { acc.x * inv, acc.y * inv, acc.z * inv, acc.w * inv };
            *(float4*)&g_Xe[e * 64 + c * 4] = r;
        }
        return;
    }

    int i = (blockIdx.x - agg_blocks) * 256 + threadIdx.x;
    if (i >= nnz) return;
    int v = vertex[i];
    int e = edges[i];
    g_veid[g_vrow[v] + g_rankv[i]] = e;
}

// ---------------- kernel F: node aggregation + residual + L2 norm -----------
__global__ void node_agg_kernel(float* __restrict__ out,
                                const float* __restrict__ homo, int n)
{
    int v = (blockIdx.x * blockDim.x + threadIdx.x) >> 5;
    if (v >= n) return;
    const int lane = threadIdx.x & 31;
    const int h = lane >> 4;
    const int c = lane & 15;

    int beg = g_vrow[v], end = g_vrow[v + 1];

    float wsum = g_att[v];
    float invw = (wsum > 0.f) ? (1.f / wsum) : 0.f;

    float4 acc = {0.f, 0.f, 0.f, 0.f};
    #pragma unroll 2
    for (int j = beg + h; j < end; j += 2) {
        int e = g_veid[j];
        float w = homo[e] * invw;
        float4 xe = *(const float4*)&g_Xe[e * 64 + c * 4];
        acc.x += w * xe.x; acc.y += w * xe.y;
        acc.z += w * xe.z; acc.w += w * xe.w;
    }
    acc.x += __shfl_xor_sync(0xffffffffu, acc.x, 16);
    acc.y += __shfl_xor_sync(0xffffffffu, acc.y, 16);
    acc.z += __shfl_xor_sync(0xffffffffu, acc.z, 16);
    acc.w += __shfl_xor_sync(0xffffffffu, acc.w, 16);

    float4 r = *(const float4*)&out[v * 64 + c * 4];
    acc.x += r.x; acc.y += r.y; acc.z += r.z; acc.w += r.w;

    float s = acc.x * acc.x + acc.y * acc.y + acc.z * acc.z + acc.w * acc.w;
    #pragma unroll
    for (int o = 8; o; o >>= 1) s += __shfl_xor_sync(0xffffffffu, s, o);

    float norm  = sqrtf(s);
    float scale = (norm > 0.f) ? (1.f / fmaxf(norm, 1e-30f)) : 0.f;
    if (h == 0) {
        float4 w = { acc.x * scale, acc.y * scale, acc.z * scale, acc.w * scale };
        *(float4*)&out[v * 64 + c * 4] = w;
    }
}

// ---------------- launch: forked graph (gemm ∥ prep chain) ------------------
extern "C" void kernel_launch(void* const* d_in, const int* in_sizes, int n_in,
                              void* d_out, int out_size)
{
    const float* X      = (const float*)d_in[0];
    const float* W      = (const float*)d_in[1];
    const float* homo   = (const float*)d_in[2];
    const int*   vertex = (const int*)  d_in[3];
    const int*   edges  = (const int*)  d_in[4];
    float*       out    = (float*)d_out;

    const int n   = in_sizes[0] / IN_CH;   // 100000
    const int nnz = in_sizes[3];           // 2000000

    // fork: gemm on side stream (depends on nothing we write)
    cudaEventRecord(g_hx.ev_fork, 0);
    cudaStreamWaitEvent(g_hx.s2, g_hx.ev_fork, 0);
    gemm_kernel<<<(n + 63) / 64, 256, 0, g_hx.s2>>>(X, W, out, n);
    cudaEventRecord(g_hx.ev_join, g_hx.s2);

    // main stream: prep chain
    zero_kernel<<<(N_NODES + 255) / 256, 256>>>();
    hist_kernel<<<(nnz / 4 + 255) / 256, 256>>>(homo, vertex, edges, nnz);
    scan_kernel<<<NTILES, 1024>>>();
    permE_kernel<<<(nnz + 255) / 256, 256>>>(vertex, edges, nnz);

    // join: edge_agg needs Xp (gemm) + g_evid (permE)
    cudaStreamWaitEvent(0, g_hx.ev_join, 0);

    const int agg_blocks  = (N_EDGES * 32 + 255) / 256;
    const int perm_blocks = (nnz + 255) / 256;
    edgeagg_permV_kernel<<<agg_blocks + perm_blocks, 256>>>(
        out, vertex, edges, nnz, agg_blocks);

    node_agg_kernel<<<((long long)n * 32 + 255) / 256, 256>>>(out, homo, n);
}

// round 17
// speedup vs baseline: 1.0185x; 1.0185x over previous
#include <cuda_runtime.h>
#include <cuda_fp16.h>
#include <stdint.h>

#define N_NODES   100000
#define N_EDGES   25000
#define NNZ_MAX   2000000
#define HO        64
#define IN_CH     64

#define TILE      4096
#define TE        ((N_EDGES + TILE - 1) / TILE)   // 7
#define TV        ((N_NODES + TILE - 1) / TILE)   // 25
#define NTILES    (TE + TV)                        // 32

// ---------------- scratch (device globals; no allocation) ----------------
__device__ __align__(16) __half g_Xe[N_EDGES * HO];   // fp16 edge means (3.2 MB)
__device__ int   g_ecnt[N_EDGES];
__device__ int   g_vcnt[N_NODES];
__device__ float g_att[N_NODES];
__device__ int   g_erow[N_EDGES + 1];
__device__ int   g_vrow[N_NODES + 1];
__device__ int   g_evid[NNZ_MAX];
__device__ int   g_veid[NNZ_MAX];
__device__ __align__(16) int g_rank[NNZ_MAX];   // packed: (rank_v << 16) | rank_e
__device__ int   g_epart[TE];
__device__ int   g_vpart[TV];
__device__ int   g_scan_arrive;

// ---------------- side stream + fork/join events (host-side, created once) --
struct HxSideStream {
    cudaStream_t s2;
    cudaEvent_t  ev_fork, ev_join;
    HxSideStream() {
        cudaStreamCreateWithFlags(&s2, cudaStreamNonBlocking);
        cudaEventCreateWithFlags(&ev_fork, cudaEventDisableTiming);
        cudaEventCreateWithFlags(&ev_join, cudaEventDisableTiming);
    }
};
static HxSideStream g_hx;

// ---------------- kernel A: zero counters + barrier flag ----------------
__global__ void zero_kernel()
{
    int idx = blockIdx.x * blockDim.x + threadIdx.x;
    if (idx == 0) g_scan_arrive = 0;
    if (idx < N_EDGES) g_ecnt[idx] = 0;
    if (idx < N_NODES) { g_vcnt[idx] = 0; g_att[idx] = 0.f; }
}

// ---------------- kernel B1: GEMM  Xp = X @ W -> out (side stream) ----------
__global__ void gemm_kernel(const float* __restrict__ X,
                            const float* __restrict__ W,
                            float* __restrict__ out, int n)
{
    __shared__ float sW[64 * 64];
    __shared__ float sX[64 * 65];

    const int t  = threadIdx.x;
    const int r0 = blockIdx.x * 64;

    #pragma unroll
    for (int idx = t; idx < 64 * 64; idx += 256) sW[idx] = W[idx];
    #pragma unroll
    for (int idx = t; idx < 64 * 64; idx += 256) {
        int r = idx >> 6, k = idx & 63;
        int gr = r0 + r;
        sX[r * 65 + k] = (gr < n) ? X[gr * 64 + k] : 0.f;
    }
    __syncthreads();

    const int row = t >> 2;
    const int q   = t & 3;

    float4 a0 = {0,0,0,0}, a1 = {0,0,0,0}, a2 = {0,0,0,0}, a3 = {0,0,0,0};
    #pragma unroll 16
    for (int k = 0; k < 64; k++) {
        float x = sX[row * 65 + k];
        const float4* w4 = (const float4*)&sW[k * 64 + q * 16];
        float4 wa = w4[0], wb = w4[1], wc = w4[2], wd = w4[3];
        a0.x += x * wa.x; a0.y += x * wa.y; a0.z += x * wa.z; a0.w += x * wa.w;
        a1.x += x * wb.x; a1.y += x * wb.y; a1.z += x * wb.z; a1.w += x * wb.w;
        a2.x += x * wc.x; a2.y += x * wc.y; a2.z += x * wc.z; a2.w += x * wc.w;
        a3.x += x * wd.x; a3.y += x * wd.y; a3.z += x * wd.z; a3.w += x * wd.w;
    }
    int gr = r0 + row;
    if (gr < n) {
        float4* o = (float4*)&out[gr * 64 + q * 16];
        o[0] = a0; o[1] = a1; o[2] = a2; o[3] = a3;
    }
}

// ---------------- kernel B2: histogram + packed rank capture ---------------
__global__ void hist_kernel(const float* __restrict__ homo,
                            const int* __restrict__ vertex,
                            const int* __restrict__ edges, int nnz)
{
    int i = (blockIdx.x * blockDim.x + threadIdx.x) * 4;
    if (i + 3 < nnz) {
        int4 v = *(const int4*)&vertex[i];
        int4 e = *(const int4*)&edges[i];
        int4 r;
        r.x = atomicAdd(&g_ecnt[e.x], 1);
        r.y = atomicAdd(&g_ecnt[e.y], 1);
        r.z = atomicAdd(&g_ecnt[e.z], 1);
        r.w = atomicAdd(&g_ecnt[e.w], 1);
        r.x |= atomicAdd(&g_vcnt[v.x], 1) << 16;
        r.y |= atomicAdd(&g_vcnt[v.y], 1) << 16;
        r.z |= atomicAdd(&g_vcnt[v.z], 1) << 16;
        r.w |= atomicAdd(&g_vcnt[v.w], 1) << 16;
        *(int4*)&g_rank[i] = r;
        atomicAdd(&g_att[v.x], homo[e.x]); atomicAdd(&g_att[v.y], homo[e.y]);
        atomicAdd(&g_att[v.z], homo[e.z]); atomicAdd(&g_att[v.w], homo[e.w]);
    } else {
        for (int k = i; k < nnz; k++) {
            int v = vertex[k], e = edges[k];
            int r = atomicAdd(&g_ecnt[e], 1);
            r |= atomicAdd(&g_vcnt[v], 1) << 16;
            g_rank[k] = r;
            atomicAdd(&g_att[v], homo[e]);
        }
    }
}

// ---------------- kernel C: fused scan (32 blocks, soft global barrier) -----
__global__ void scan_kernel()
{
    const bool is_e = blockIdx.x < TE;
    const int  tile = is_e ? blockIdx.x : blockIdx.x - TE;
    const int  n    = is_e ? N_EDGES : N_NODES;
    const int  nt   = is_e ? TE : TV;
    const int* __restrict__ cnt  = is_e ? g_ecnt : g_vcnt;
    int* __restrict__ part       = is_e ? g_epart : g_vpart;
    int* __restrict__ row        = is_e ? g_erow : g_vrow;

    __shared__ int s_wsum[32];
    __shared__ int s_tile_off;
    const int lane = threadIdx.x & 31;
    const int wid  = threadIdx.x >> 5;

    int base = tile * TILE + threadIdx.x * 4;
    int c[4];
    int s = 0;
    #pragma unroll
    for (int k = 0; k < 4; k++) {
        int i = base + k;
        c[k] = (i < n) ? cnt[i] : 0;
        s += c[k];
    }
    int v = s;
    #pragma unroll
    for (int o = 1; o < 32; o <<= 1) {
        int t = __shfl_up_sync(0xffffffffu, v, o);
        if (lane >= o) v += t;
    }
    if (lane == 31) s_wsum[wid] = v;
    __syncthreads();

    if (wid == 0) {
        int w = s_wsum[lane];
        int tot = w;
        #pragma unroll
        for (int o = 16; o; o >>= 1) tot += __shfl_xor_sync(0xffffffffu, tot, o);
        if (lane == 0) {
            part[tile] = tot;
            __threadfence();
            atomicAdd(&g_scan_arrive, 1);
        }
    }
    if (threadIdx.x == 0) {
        while (atomicAdd(&g_scan_arrive, 0) < NTILES) { }
    }
    __syncthreads();
    __threadfence();

    if (wid == 0) {
        const int* p_arr = is_e ? g_epart : g_vpart;
        int p = (lane < nt) ? p_arr[lane] : 0;
        int incl = p;
        #pragma unroll
        for (int o = 1; o < 32; o <<= 1) {
            int t = __shfl_up_sync(0xffffffffu, incl, o);
            if (lane >= o) incl += t;
        }
        if (lane == tile) s_tile_off = incl - p;
        if (tile == 0 && lane == nt - 1) row[n] = incl;

        int w = s_wsum[lane];
        int u = w;
        #pragma unroll
        for (int o = 1; o < 32; o <<= 1) {
            int t = __shfl_up_sync(0xffffffffu, u, o);
            if (lane >= o) u += t;
        }
        s_wsum[lane] = u - w;
    }
    __syncthreads();

    int excl = s_tile_off + s_wsum[wid] + (v - s);
    #pragma unroll
    for (int k = 0; k < 4; k++) {
        int i = base + k;
        if (i < n) row[i] = excl;
        excl += c[k];
    }
}

// ---------------- kernel D: edge-side scatter (atomic-free) -----------------
__global__ void permE_kernel(const int* __restrict__ vertex,
                             const int* __restrict__ edges, int nnz)
{
    int i = blockIdx.x * blockDim.x + threadIdx.x;
    if (i >= nnz) return;
    int v = vertex[i];
    int e = edges[i];
    g_evid[g_erow[e] + (g_rank[i] & 0xffff)] = v;
}

// ---------------- kernel E: fused edge_agg (fp16 Xe out) + permV ------------
__global__ void edgeagg_permV_kernel(const float* __restrict__ Xp,
                                     const int* __restrict__ vertex,
                                     const int* __restrict__ edges,
                                     int nnz, int agg_blocks)
{
    if (blockIdx.x < agg_blocks) {
        int e = (blockIdx.x * blockDim.x + threadIdx.x) >> 5;
        if (e >= N_EDGES) return;
        const int lane = threadIdx.x & 31;
        const int h = lane >> 4;
        const int c = lane & 15;

        int beg = g_erow[e], end = g_erow[e + 1];
        float4 acc = {0.f, 0.f, 0.f, 0.f};

        #pragma unroll 2
        for (int j = beg + h; j < end; j += 2) {
            int v = g_evid[j];
            float4 x = *(const float4*)&Xp[v * 64 + c * 4];
            acc.x += x.x; acc.y += x.y; acc.z += x.z; acc.w += x.w;
        }
        acc.x += __shfl_xor_sync(0xffffffffu, acc.x, 16);
        acc.y += __shfl_xor_sync(0xffffffffu, acc.y, 16);
        acc.z += __shfl_xor_sync(0xffffffffu, acc.z, 16);
        acc.w += __shfl_xor_sync(0xffffffffu, acc.w, 16);

        int deg = end - beg;
        float inv = (deg > 0) ? (1.f / (float)deg) : 0.f;
        if (h == 0) {
            __half2 r0 = __floats2half2_rn(acc.x * inv, acc.y * inv);
            __half2 r1 = __floats2half2_rn(acc.z * inv, acc.w * inv);
            uint2 w;
            w.x = *(uint32_t*)&r0;
            w.y = *(uint32_t*)&r1;
            *(uint2*)&g_Xe[e * 64 + c * 4] = w;
        }
        return;
    }

    int i = (blockIdx.x - agg_blocks) * 256 + threadIdx.x;
    if (i >= nnz) return;
    int v = vertex[i];
    int e = edges[i];
    g_veid[g_vrow[v] + (((unsigned)g_rank[i]) >> 16)] = e;
}

// ---------------- kernel F: node aggregation (fp16 gather) + residual + norm
__global__ void node_agg_kernel(float* __restrict__ out,
                                const float* __restrict__ homo, int n)
{
    int v = (blockIdx.x * blockDim.x + threadIdx.x) >> 5;
    if (v >= n) return;
    const int lane = threadIdx.x & 31;
    const int h = lane >> 4;
    const int c = lane & 15;

    int beg = g_vrow[v], end = g_vrow[v + 1];

    float wsum = g_att[v];
    float invw = (wsum > 0.f) ? (1.f / wsum) : 0.f;

    float4 acc = {0.f, 0.f, 0.f, 0.f};
    #pragma unroll 2
    for (int j = beg + h; j < end; j += 2) {
        int e = g_veid[j];
        float w = homo[e] * invw;
        uint2 u = *(const uint2*)&g_Xe[e * 64 + c * 4];
        float2 f0 = __half22float2(*(__half2*)&u.x);
        float2 f1 = __half22float2(*(__half2*)&u.y);
        acc.x += w * f0.x; acc.y += w * f0.y;
        acc.z += w * f1.x; acc.w += w * f1.y;
    }
    acc.x += __shfl_xor_sync(0xffffffffu, acc.x, 16);
    acc.y += __shfl_xor_sync(0xffffffffu, acc.y, 16);
    acc.z += __shfl_xor_sync(0xffffffffu, acc.z, 16);
    acc.w += __shfl_xor_sync(0xffffffffu, acc.w, 16);

    // residual (Xp fp32 lives in out)
    float4 r = *(const float4*)&out[v * 64 + c * 4];
    acc.x += r.x; acc.y += r.y; acc.z += r.z; acc.w += r.w;

    // row-L2 norm: halves identical; butterfly within half
    float s = acc.x * acc.x + acc.y * acc.y + acc.z * acc.z + acc.w * acc.w;
    #pragma unroll
    for (int o = 8; o; o >>= 1) s += __shfl_xor_sync(0xffffffffu, s, o);

    float norm  = sqrtf(s);
    float scale = (norm > 0.f) ? (1.f / fmaxf(norm, 1e-30f)) : 0.f;
    if (h == 0) {
        float4 w = { acc.x * scale, acc.y * scale, acc.z * scale, acc.w * scale };
        *(float4*)&out[v * 64 + c * 4] = w;
    }
}

// ---------------- launch: forked graph (gemm ∥ prep chain) ------------------
extern "C" void kernel_launch(void* const* d_in, const int* in_sizes, int n_in,
                              void* d_out, int out_size)
{
    const float* X      = (const float*)d_in[0];
    const float* W      = (const float*)d_in[1];
    const float* homo   = (const float*)d_in[2];
    const int*   vertex = (const int*)  d_in[3];
    const int*   edges  = (const int*)  d_in[4];
    float*       out    = (float*)d_out;

    const int n   = in_sizes[0] / IN_CH;   // 100000
    const int nnz = in_sizes[3];           // 2000000

    // fork: gemm on side stream (depends on nothing we write)
    cudaEventRecord(g_hx.ev_fork, 0);
    cudaStreamWaitEvent(g_hx.s2, g_hx.ev_fork, 0);
    gemm_kernel<<<(n + 63) / 64, 256, 0, g_hx.s2>>>(X, W, out, n);
    cudaEventRecord(g_hx.ev_join, g_hx.s2);

    // main stream: prep chain
    zero_kernel<<<(N_NODES + 255) / 256, 256>>>();
    hist_kernel<<<(nnz / 4 + 255) / 256, 256>>>(homo, vertex, edges, nnz);
    scan_kernel<<<NTILES, 1024>>>();
    permE_kernel<<<(nnz + 255) / 256, 256>>>(vertex, edges, nnz);

    // join: edge_agg needs Xp (gemm) + g_evid (permE)
    cudaStreamWaitEvent(0, g_hx.ev_join, 0);

    const int agg_blocks  = (N_EDGES * 32 + 255) / 256;
    const int perm_blocks = (nnz + 255) / 256;
    edgeagg_permV_kernel<<<agg_blocks + perm_blocks, 256>>>(
        out, vertex, edges, nnz, agg_blocks);

    node_agg_kernel<<<((long long)n * 32 + 255) / 256, 256>>>(out, homo, n);
}